// round 5
// baseline (speedup 1.0000x reference)
#include <cuda_runtime.h>
#include <cuda_fp16.h>
#include <cstdint>

#define T_TOK 4096
#define DMODEL 768
#define HID 2048
#define NE 8
#define ALPHA 0.05f

#define AST 72          // A smem row stride in halves (144B; ldmatrix conflict-free)
#define BST 72          // B smem row stride in halves
#define GEMM_SMEM (2 * 128 * AST * 2 + 2 * 64 * BST * 2)   // 55296 B

// ---------------- scratch ----------------------------------------------------
__device__ int   g_expert[T_TOK];
__device__ float g_gate[T_TOK];
__device__ int   g_counts[NE];
__device__ int   g_off[NE + 1];
__device__ int   g_cursor[NE];
__device__ float g_ce[NE];
__device__ int   g_tok[T_TOK];
__device__ __align__(16) __half g_xg[(size_t)T_TOK * DMODEL];  // fp16 tokens, expert-sorted
__device__ __align__(16) __half g_u[(size_t)T_TOK * HID];      // X@Wu
__device__ __align__(16) __half g_h[(size_t)T_TOK * HID];      // silu(u)*v

// ---------------- helpers ----------------------------------------------------
__device__ __forceinline__ uint32_t smem_u32(const void* p) {
    uint32_t a;
    asm("{ .reg .u64 t; cvta.to.shared.u64 t, %1; cvt.u32.u64 %0, t; }" : "=r"(a) : "l"(p));
    return a;
}
__device__ __forceinline__ uint32_t pk(float a, float b) {
    __half2 h = __floats2half2_rn(a, b);
    return *reinterpret_cast<uint32_t*>(&h);
}
__device__ __forceinline__ void cpa16(uint32_t dst, const void* src, bool valid) {
    int sz = valid ? 16 : 0;
    asm volatile("cp.async.cg.shared.global [%0], [%1], 16, %2;\n"
                 :: "r"(dst), "l"(src), "r"(sz) : "memory");
}
#define CP_COMMIT() asm volatile("cp.async.commit_group;" ::: "memory")
#define CP_WAIT0()  asm volatile("cp.async.wait_group 0;" ::: "memory")

#define LDSM_X4(r0, r1, r2, r3, a)                                              \
    asm volatile("ldmatrix.sync.aligned.m8n8.x4.shared.b16 {%0,%1,%2,%3}, [%4];"\
                 : "=r"(r0), "=r"(r1), "=r"(r2), "=r"(r3) : "r"(a))
#define LDSM_X4T(r0, r1, r2, r3, a)                                             \
    asm volatile("ldmatrix.sync.aligned.m8n8.x4.trans.shared.b16 {%0,%1,%2,%3}, [%4];"\
                 : "=r"(r0), "=r"(r1), "=r"(r2), "=r"(r3) : "r"(a))

#define MMA16816(d, a, b0, b1)                                                  \
    asm volatile("mma.sync.aligned.m16n8k16.row.col.f32.f16.f16.f32 "           \
                 "{%0,%1,%2,%3},{%4,%5,%6,%7},{%8,%9},{%0,%1,%2,%3};"           \
                 : "+f"((d)[0]), "+f"((d)[1]), "+f"((d)[2]), "+f"((d)[3])       \
                 : "r"((a)[0]), "r"((a)[1]), "r"((a)[2]), "r"((a)[3]),          \
                   "r"(b0), "r"(b1))

// ---------------- small kernels ----------------------------------------------
__global__ void init_kernel() {
    int i = threadIdx.x;
    if (i < NE) { g_counts[i] = 0; g_ce[i] = 0.f; }
}

__global__ void gate_kernel(const float* __restrict__ x,
                            const float* __restrict__ wgw,
                            const float* __restrict__ wgb) {
    __shared__ float s_ce[NE];
    __shared__ int   s_cnt[NE];
    int tid = threadIdx.x;
    if (tid < NE) { s_ce[tid] = 0.f; s_cnt[tid] = 0; }
    __syncthreads();

    int warp = tid >> 5, lane = tid & 31;
    int t = blockIdx.x * 8 + warp;

    float acc[NE];
#pragma unroll
    for (int e = 0; e < NE; e++) acc[e] = 0.f;
    const float* xr = x + (size_t)t * DMODEL;
    for (int i = lane; i < DMODEL; i += 32) {
        float xv = xr[i];
#pragma unroll
        for (int e = 0; e < NE; e++) acc[e] += xv * wgw[e * DMODEL + i];
    }
#pragma unroll
    for (int e = 0; e < NE; e++)
#pragma unroll
        for (int o = 16; o > 0; o >>= 1) acc[e] += __shfl_xor_sync(0xFFFFFFFFu, acc[e], o);

    if (lane == 0) {
        float mx = -1e30f; int be = 0;
#pragma unroll
        for (int e = 0; e < NE; e++) {
            acc[e] += wgb[e];
            if (acc[e] > mx) { mx = acc[e]; be = e; }
        }
        float p[NE]; float s = 0.f;
#pragma unroll
        for (int e = 0; e < NE; e++) { p[e] = __expf(acc[e] - mx); s += p[e]; }
        float inv = 1.f / s;
#pragma unroll
        for (int e = 0; e < NE; e++) { p[e] *= inv; atomicAdd(&s_ce[e], p[e]); }
        g_expert[t] = be;
        g_gate[t]   = p[be];
        atomicAdd(&s_cnt[be], 1);
    }
    __syncthreads();
    if (tid < NE) { atomicAdd(&g_ce[tid], s_ce[tid]); atomicAdd(&g_counts[tid], s_cnt[tid]); }
}

__global__ void scan_kernel() {
    if (threadIdx.x == 0) {
        int s = 0;
        for (int e = 0; e < NE; e++) { g_off[e] = s; g_cursor[e] = s; s += g_counts[e]; }
        g_off[NE] = s;
    }
}

__global__ void gather_kernel(const float* __restrict__ x) {
    __shared__ int s_pos;
    int t = blockIdx.x;
    if (threadIdx.x == 0) {
        int e = g_expert[t];
        int pos = atomicAdd(&g_cursor[e], 1);
        g_tok[pos] = t;
        s_pos = pos;
    }
    __syncthreads();
    int pos = s_pos;
    const float4* src = (const float4*)(x + (size_t)t * DMODEL);
    __half2* dst = (__half2*)(g_xg + (size_t)pos * DMODEL);
    for (int i = threadIdx.x; i < DMODEL / 4; i += blockDim.x) {
        float4 v = src[i];
        dst[i * 2 + 0] = __floats2half2_rn(v.x, v.y);
        dst[i * 2 + 1] = __floats2half2_rn(v.z, v.w);
    }
}

// ---------------- unified GEMM ------------------------------------------------
// MODE 0: g_u   = Xg @ B          (B=Wu, K=DMODEL, N=HID)
// MODE 2: g_h   = silu(g_u) * (Xg @ B)   (B=Wv)
// MODE 1: out[tok] = gate * (g_h @ B)    (B=Wd, K=HID, N=DMODEL)
// BM=128, BN=64, BK=64; 8 warps (4m x 2n), warp tile 32x32; 2-stage smem,
// fragment double-buffered; grid.x = m-tile (weight L2 reuse across m).
template <int MODE>
__global__ __launch_bounds__(256, 2) void gemm_k(const float* __restrict__ B,
                                                 float* __restrict__ out) {
    constexpr int KDIM = (MODE == 1) ? HID : DMODEL;
    constexpr int NDIM = (MODE == 1) ? DMODEL : HID;
    constexpr int NCH  = KDIM / 64;

    int e    = blockIdx.z;
    int mEnd = g_off[e + 1];
    int m0   = g_off[e] + blockIdx.x * 128;
    if (m0 >= mEnd) return;
    int n0 = blockIdx.y * 64;

    extern __shared__ __align__(16) char smem[];
    __half* As = (__half*)smem;                        // 2 x 128 x AST
    __half* Bsm = (__half*)(smem + 2 * 128 * AST * 2); // 2 x 64 x BST

    int tid = threadIdx.x, lane = tid & 31, wid = tid >> 5;
    int wm = wid & 3, wn = wid >> 2;
    int lg = lane >> 2, lt = lane & 3;

    uint32_t aA[2] = { smem_u32(As), smem_u32(As + 128 * AST) };
    uint32_t aB[2] = { smem_u32(Bsm), smem_u32(Bsm + 64 * BST) };

    const __half* Asrc = (MODE == 1) ? g_h : g_xg;
    const float*  BE   = B + (size_t)e * KDIM * NDIM;

    float acc[2][4][4];
#pragma unroll
    for (int mt = 0; mt < 2; mt++)
#pragma unroll
        for (int nt = 0; nt < 4; nt++)
#pragma unroll
            for (int r = 0; r < 4; r++) acc[mt][nt][r] = 0.f;

    int brow = tid >> 2, bcol = (tid & 3) * 16;
    uint32_t pb[8];

    auto issueA = [&](int c, int st) {
#pragma unroll
        for (int q = 0; q < 4; q++) {
            int sidx = tid + q * 256;
            int row = sidx >> 3, sg = sidx & 7;
            int gm = m0 + row;
            bool v = gm < mEnd;
            uint32_t dst = aA[st] + (uint32_t)(row * AST + sg * 8) * 2;
            const __half* src = &Asrc[(size_t)(v ? gm : m0) * KDIM + c * 64 + sg * 8];
            cpa16(dst, src, v);
        }
    };
    auto ldgB = [&](int c) {
        const float* rb = &BE[(size_t)(c * 64 + brow) * NDIM + n0 + bcol];
#pragma unroll
        for (int q = 0; q < 4; q++) {
            float4 f = *(const float4*)(rb + q * 4);
            pb[q * 2 + 0] = pk(f.x, f.y);
            pb[q * 2 + 1] = pk(f.z, f.w);
        }
    };
    auto stsB = [&](int st) {
        __half* d = &Bsm[(size_t)st * 64 * BST + brow * BST + bcol];
        *(uint4*)d       = make_uint4(pb[0], pb[1], pb[2], pb[3]);
        *(uint4*)(d + 8) = make_uint4(pb[4], pb[5], pb[6], pb[7]);
    };
    auto ldA = [&](int st, int s, uint32_t a[2][4]) {
#pragma unroll
        for (int mt = 0; mt < 2; mt++) {
            uint32_t ad = aA[st] + (uint32_t)((wm * 32 + mt * 16 + (lane & 15)) * AST
                                              + s * 16 + (lane >> 4) * 8) * 2;
            LDSM_X4(a[mt][0], a[mt][1], a[mt][2], a[mt][3], ad);
        }
    };
    auto ldB = [&](int st, int s, uint32_t b[2][4]) {
#pragma unroll
        for (int np = 0; np < 2; np++) {
            uint32_t bd = aB[st] + (uint32_t)((s * 16 + (lane & 15)) * BST
                                              + wn * 32 + np * 16 + (lane >> 4) * 8) * 2;
            LDSM_X4T(b[np][0], b[np][1], b[np][2], b[np][3], bd);
        }
    };
    auto compute = [&](int st) {
        uint32_t a[2][2][4], b[2][2][4];
        ldA(st, 0, a[0]);
        ldB(st, 0, b[0]);
#pragma unroll
        for (int s = 0; s < 4; s++) {
            int cur = s & 1, nxt = cur ^ 1;
            if (s < 3) { ldA(st, s + 1, a[nxt]); ldB(st, s + 1, b[nxt]); }
#pragma unroll
            for (int np = 0; np < 2; np++)
#pragma unroll
                for (int mt = 0; mt < 2; mt++) {
                    MMA16816(acc[mt][np * 2 + 0], a[cur][mt], b[cur][np][0], b[cur][np][1]);
                    MMA16816(acc[mt][np * 2 + 1], a[cur][mt], b[cur][np][2], b[cur][np][3]);
                }
        }
    };

    issueA(0, 0); CP_COMMIT();
    ldgB(0); stsB(0);
    CP_WAIT0(); __syncthreads();

    for (int c = 0; c < NCH; c++) {
        int buf = c & 1;
        bool pf = (c + 1) < NCH;
        if (pf) { issueA(c + 1, buf ^ 1); CP_COMMIT(); ldgB(c + 1); }
        compute(buf);
        if (pf) { stsB(buf ^ 1); CP_WAIT0(); }
        __syncthreads();
    }

    // ---- epilogue ----
#pragma unroll
    for (int mt = 0; mt < 2; mt++) {
#pragma unroll
        for (int nt = 0; nt < 4; nt++) {
            int row0 = m0 + wm * 32 + mt * 16 + lg;
            int col  = n0 + wn * 32 + nt * 8 + lt * 2;
#pragma unroll
            for (int hh = 0; hh < 2; hh++) {
                int row = row0 + hh * 8;
                if (row >= mEnd) continue;
                float c0 = acc[mt][nt][hh * 2 + 0], c1 = acc[mt][nt][hh * 2 + 1];
                if (MODE == 0) {
                    *(__half2*)&g_u[(size_t)row * HID + col] = __floats2half2_rn(c0, c1);
                } else if (MODE == 2) {
                    float2 uf = __half22float2(*(const __half2*)&g_u[(size_t)row * HID + col]);
                    float h0 = uf.x / (1.f + __expf(-uf.x)) * c0;
                    float h1 = uf.y / (1.f + __expf(-uf.y)) * c1;
                    *(__half2*)&g_h[(size_t)row * HID + col] = __floats2half2_rn(h0, h1);
                } else {
                    int token = g_tok[row];
                    float gate = g_gate[token];
                    *(float2*)&out[(size_t)token * DMODEL + col] =
                        make_float2(c0 * gate, c1 * gate);
                }
            }
        }
    }
}

// ---------------- aux --------------------------------------------------------
__global__ void aux_kernel(float* __restrict__ out) {
    float s = 0.f;
    for (int e = 0; e < NE; e++) {
        float me = (float)g_counts[e] / (float)T_TOK;
        float ce = g_ce[e] / (float)T_TOK;
        s += me * ce;
    }
    out[(size_t)T_TOK * DMODEL] = ALPHA * NE * s;
}

// ---------------- launch -----------------------------------------------------
extern "C" void kernel_launch(void* const* d_in, const int* in_sizes, int n_in,
                              void* d_out, int out_size) {
    const float* x   = (const float*)d_in[0];
    const float* wgw = (const float*)d_in[1];
    const float* wgb = (const float*)d_in[2];
    const float* Wu  = (const float*)d_in[3];
    const float* Wv  = (const float*)d_in[4];
    const float* Wd  = (const float*)d_in[5];
    float* out = (float*)d_out;

    static bool attr_set = false;
    if (!attr_set) {
        cudaFuncSetAttribute(gemm_k<0>, cudaFuncAttributeMaxDynamicSharedMemorySize, GEMM_SMEM);
        cudaFuncSetAttribute(gemm_k<2>, cudaFuncAttributeMaxDynamicSharedMemorySize, GEMM_SMEM);
        cudaFuncSetAttribute(gemm_k<1>, cudaFuncAttributeMaxDynamicSharedMemorySize, GEMM_SMEM);
        attr_set = true;
    }

    init_kernel<<<1, 32>>>();
    gate_kernel<<<T_TOK / 8, 256>>>(x, wgw, wgb);
    scan_kernel<<<1, 1>>>();
    gather_kernel<<<T_TOK, 192>>>(x);
    gemm_k<0><<<dim3(32, HID / 64, NE), 256, GEMM_SMEM>>>(Wu, nullptr);
    gemm_k<2><<<dim3(32, HID / 64, NE), 256, GEMM_SMEM>>>(Wv, nullptr);
    gemm_k<1><<<dim3(32, DMODEL / 64, NE), 256, GEMM_SMEM>>>(Wd, out);
    aux_kernel<<<1, 1>>>(out);
}

// round 6
// speedup vs baseline: 1.2386x; 1.2386x over previous
#include <cuda_runtime.h>
#include <cuda_fp16.h>
#include <cstdint>

#define T_TOK 4096
#define DMODEL 768
#define HID 2048
#define NE 8
#define ALPHA 0.05f

#define AST 40          // A smem row stride in halves (80B, conflict-free for ldmatrix)
#define BST 72          // B smem row stride in halves (144B, conflict-free for ldmatrix.trans)
#define NC_UP (DMODEL / 32)   // 24 k-chunks
#define NC_DN (HID / 32)      // 64 k-chunks

// ---------------- scratch ----------------------------------------------------
__device__ int   g_expert[T_TOK];
__device__ float g_gate[T_TOK];
__device__ int   g_counts[NE];
__device__ int   g_off[NE + 1];
__device__ int   g_cursor[NE];
__device__ float g_ce[NE];
__device__ int   g_tok[T_TOK];
__device__ __align__(16) __half g_xg[(size_t)T_TOK * DMODEL];  // fp16 tokens, expert-sorted
__device__ __align__(16) __half g_h[(size_t)T_TOK * HID];      // fp16 silu(u)*v

// ---------------- helpers ----------------------------------------------------
__device__ __forceinline__ uint32_t smem_u32(const void* p) {
    uint32_t a;
    asm("{ .reg .u64 t; cvta.to.shared.u64 t, %1; cvt.u32.u64 %0, t; }" : "=r"(a) : "l"(p));
    return a;
}
__device__ __forceinline__ uint32_t pk(float a, float b) {
    __half2 h = __floats2half2_rn(a, b);
    return *reinterpret_cast<uint32_t*>(&h);
}
__device__ __forceinline__ void cpa16(uint32_t dst, const void* src, bool valid) {
    int sz = valid ? 16 : 0;
    asm volatile("cp.async.cg.shared.global [%0], [%1], 16, %2;\n"
                 :: "r"(dst), "l"(src), "r"(sz) : "memory");
}
#define CP_COMMIT() asm volatile("cp.async.commit_group;" ::: "memory")
#define CP_WAIT0()  asm volatile("cp.async.wait_group 0;" ::: "memory")

#define LDSM_X4(r0, r1, r2, r3, a)                                              \
    asm volatile("ldmatrix.sync.aligned.m8n8.x4.shared.b16 {%0,%1,%2,%3}, [%4];"\
                 : "=r"(r0), "=r"(r1), "=r"(r2), "=r"(r3) : "r"(a))
#define LDSM_X4T(r0, r1, r2, r3, a)                                             \
    asm volatile("ldmatrix.sync.aligned.m8n8.x4.trans.shared.b16 {%0,%1,%2,%3}, [%4];"\
                 : "=r"(r0), "=r"(r1), "=r"(r2), "=r"(r3) : "r"(a))

#define MMA16816(d, a, b0, b1)                                                  \
    asm volatile("mma.sync.aligned.m16n8k16.row.col.f32.f16.f16.f32 "           \
                 "{%0,%1,%2,%3},{%4,%5,%6,%7},{%8,%9},{%0,%1,%2,%3};"           \
                 : "+f"((d)[0]), "+f"((d)[1]), "+f"((d)[2]), "+f"((d)[3])       \
                 : "r"((a)[0]), "r"((a)[1]), "r"((a)[2]), "r"((a)[3]),          \
                   "r"(b0), "r"(b1))

// ---------------- small kernels ----------------------------------------------
__global__ void init_kernel() {
    int i = threadIdx.x;
    if (i < NE) { g_counts[i] = 0; g_ce[i] = 0.f; }
}

__global__ void gate_kernel(const float* __restrict__ x,
                            const float* __restrict__ wgw,
                            const float* __restrict__ wgb) {
    __shared__ float s_ce[NE];
    __shared__ int   s_cnt[NE];
    int tid = threadIdx.x;
    if (tid < NE) { s_ce[tid] = 0.f; s_cnt[tid] = 0; }
    __syncthreads();

    int warp = tid >> 5, lane = tid & 31;
    int t = blockIdx.x * 8 + warp;

    float acc[NE];
#pragma unroll
    for (int e = 0; e < NE; e++) acc[e] = 0.f;
    const float* xr = x + (size_t)t * DMODEL;
    for (int i = lane; i < DMODEL; i += 32) {
        float xv = xr[i];
#pragma unroll
        for (int e = 0; e < NE; e++) acc[e] += xv * wgw[e * DMODEL + i];
    }
#pragma unroll
    for (int e = 0; e < NE; e++)
#pragma unroll
        for (int o = 16; o > 0; o >>= 1) acc[e] += __shfl_xor_sync(0xFFFFFFFFu, acc[e], o);

    if (lane == 0) {
        float mx = -1e30f; int be = 0;
#pragma unroll
        for (int e = 0; e < NE; e++) {
            acc[e] += wgb[e];
            if (acc[e] > mx) { mx = acc[e]; be = e; }
        }
        float p[NE]; float s = 0.f;
#pragma unroll
        for (int e = 0; e < NE; e++) { p[e] = __expf(acc[e] - mx); s += p[e]; }
        float inv = 1.f / s;
#pragma unroll
        for (int e = 0; e < NE; e++) { p[e] *= inv; atomicAdd(&s_ce[e], p[e]); }
        g_expert[t] = be;
        g_gate[t]   = p[be];
        atomicAdd(&s_cnt[be], 1);
    }
    __syncthreads();
    if (tid < NE) { atomicAdd(&g_ce[tid], s_ce[tid]); atomicAdd(&g_counts[tid], s_cnt[tid]); }
}

__global__ void scan_kernel() {
    if (threadIdx.x == 0) {
        int s = 0;
        for (int e = 0; e < NE; e++) { g_off[e] = s; g_cursor[e] = s; s += g_counts[e]; }
        g_off[NE] = s;
    }
}

__global__ void gather_kernel(const float* __restrict__ x) {
    __shared__ int s_pos;
    int t = blockIdx.x;
    if (threadIdx.x == 0) {
        int e = g_expert[t];
        int pos = atomicAdd(&g_cursor[e], 1);
        g_tok[pos] = t;
        s_pos = pos;
    }
    __syncthreads();
    int pos = s_pos;
    const float4* src = (const float4*)(x + (size_t)t * DMODEL);
    __half2* dst = (__half2*)(g_xg + (size_t)pos * DMODEL);
    for (int i = threadIdx.x; i < DMODEL / 4; i += blockDim.x) {
        float4 v = src[i];
        dst[i * 2 + 0] = __floats2half2_rn(v.x, v.y);
        dst[i * 2 + 1] = __floats2half2_rn(v.z, v.w);
    }
}

// ---------------- up: H = silu(Xe@Wu)*(Xe@Wv), fp16 mma + ldmatrix ----------
// BM=128, BN=64, BK=32. 8 warps (4m x 2n), warp tile 32x32.
// grid.x = m-tile (fastest) so CTAs sharing a weight slice are wave-adjacent.
__global__ __launch_bounds__(256) void up_mma(const float* __restrict__ Wu,
                                              const float* __restrict__ Wv) {
    int e    = blockIdx.z;
    int mEnd = g_off[e + 1];
    int m0   = g_off[e] + blockIdx.x * 128;
    if (m0 >= mEnd) return;
    int n0 = blockIdx.y * 64;

    __shared__ __align__(16) __half As[2][128 * AST];
    __shared__ __align__(16) __half Bu[2][32 * BST];
    __shared__ __align__(16) __half Bv[2][32 * BST];

    int tid = threadIdx.x, lane = tid & 31, wid = tid >> 5;
    int wm = wid & 3, wn = wid >> 2;
    int lg = lane >> 2, lt = lane & 3;

    uint32_t aA[2] = { smem_u32(As[0]), smem_u32(As[1]) };
    uint32_t aU[2] = { smem_u32(Bu[0]), smem_u32(Bu[1]) };
    uint32_t aV[2] = { smem_u32(Bv[0]), smem_u32(Bv[1]) };

    const float* WuE = Wu + (size_t)e * DMODEL * HID;
    const float* WvE = Wv + (size_t)e * DMODEL * HID;

    float au[2][4][4], av[2][4][4];
#pragma unroll
    for (int mt = 0; mt < 2; mt++)
#pragma unroll
        for (int nt = 0; nt < 4; nt++)
#pragma unroll
            for (int r = 0; r < 4; r++) { au[mt][nt][r] = 0.f; av[mt][nt][r] = 0.f; }

    int brow = tid >> 3, bcol = (tid & 7) * 8;     // B loader: k-row, 8 n-cols
    float pu[8], pv[8];

    auto issueA = [&](int c, int st) {
#pragma unroll
        for (int q = 0; q < 2; q++) {
            int sidx = tid + q * 256;
            int row = sidx >> 2, sg = sidx & 3;
            int gm = m0 + row;
            bool v = gm < mEnd;
            uint32_t dst = aA[st] + (uint32_t)(row * AST + sg * 8) * 2;
            const __half* src = &g_xg[(size_t)(v ? gm : m0) * DMODEL + c * 32 + sg * 8];
            cpa16(dst, src, v);
        }
    };
    auto ldgB = [&](int c) {
        const float* ru = &WuE[(size_t)(c * 32 + brow) * HID + n0 + bcol];
        const float* rv = &WvE[(size_t)(c * 32 + brow) * HID + n0 + bcol];
        *(float4*)&pu[0] = *(const float4*)ru;  *(float4*)&pu[4] = *(const float4*)(ru + 4);
        *(float4*)&pv[0] = *(const float4*)rv;  *(float4*)&pv[4] = *(const float4*)(rv + 4);
    };
    auto stsB = [&](int st) {
        *(uint4*)&Bu[st][brow * BST + bcol] =
            make_uint4(pk(pu[0], pu[1]), pk(pu[2], pu[3]), pk(pu[4], pu[5]), pk(pu[6], pu[7]));
        *(uint4*)&Bv[st][brow * BST + bcol] =
            make_uint4(pk(pv[0], pv[1]), pk(pv[2], pv[3]), pk(pv[4], pv[5]), pk(pv[6], pv[7]));
    };
    auto ldFragA = [&](int st, int s, uint32_t a[2][4]) {
#pragma unroll
        for (int mt = 0; mt < 2; mt++) {
            uint32_t ad = aA[st] + (uint32_t)(((wm * 32 + mt * 16 + (lane & 15)) * AST)
                                              + s * 16 + (lane >> 4) * 8) * 2;
            LDSM_X4(a[mt][0], a[mt][1], a[mt][2], a[mt][3], ad);
        }
    };
    auto ldFragB = [&](int st, int s, uint32_t u[2][4], uint32_t v[2][4]) {
#pragma unroll
        for (int np = 0; np < 2; np++) {
            uint32_t boff = (uint32_t)(((s * 16 + (lane & 15)) * BST)
                                       + wn * 32 + np * 16 + (lane >> 4) * 8) * 2;
            LDSM_X4T(u[np][0], u[np][1], u[np][2], u[np][3], aU[st] + boff);
            LDSM_X4T(v[np][0], v[np][1], v[np][2], v[np][3], aV[st] + boff);
        }
    };
    auto compute = [&](int st) {
        uint32_t a[2][2][4], bu[2][2][4], bv[2][2][4];
        ldFragA(st, 0, a[0]);
        ldFragB(st, 0, bu[0], bv[0]);
#pragma unroll
        for (int s = 0; s < 2; s++) {
            int cur = s & 1, nxt = cur ^ 1;
            if (s < 1) { ldFragA(st, s + 1, a[nxt]); ldFragB(st, s + 1, bu[nxt], bv[nxt]); }
#pragma unroll
            for (int np = 0; np < 2; np++)
#pragma unroll
                for (int mt = 0; mt < 2; mt++) {
                    MMA16816(au[mt][np * 2 + 0], a[cur][mt], bu[cur][np][0], bu[cur][np][1]);
                    MMA16816(au[mt][np * 2 + 1], a[cur][mt], bu[cur][np][2], bu[cur][np][3]);
                    MMA16816(av[mt][np * 2 + 0], a[cur][mt], bv[cur][np][0], bv[cur][np][1]);
                    MMA16816(av[mt][np * 2 + 1], a[cur][mt], bv[cur][np][2], bv[cur][np][3]);
                }
        }
    };

    issueA(0, 0); ldgB(0); stsB(0);
    CP_COMMIT(); CP_WAIT0(); __syncthreads();

    for (int c = 0; c < NC_UP; c++) {
        int buf = c & 1;
        bool pf = (c + 1) < NC_UP;
        if (pf) { issueA(c + 1, buf ^ 1); ldgB(c + 1); }
        compute(buf);
        if (pf) stsB(buf ^ 1);
        CP_COMMIT(); CP_WAIT0(); __syncthreads();
    }

    // epilogue: silu(u)*v -> g_h (fp16)
#pragma unroll
    for (int mt = 0; mt < 2; mt++) {
#pragma unroll
        for (int nt = 0; nt < 4; nt++) {
            int row0 = m0 + wm * 32 + mt * 16 + lg;
            int col  = n0 + wn * 32 + nt * 8 + lt * 2;
            if (row0 < mEnd) {
                float u0 = au[mt][nt][0], u1 = au[mt][nt][1];
                float h0 = u0 / (1.f + __expf(-u0)) * av[mt][nt][0];
                float h1 = u1 / (1.f + __expf(-u1)) * av[mt][nt][1];
                *(__half2*)&g_h[(size_t)row0 * HID + col] = __floats2half2_rn(h0, h1);
            }
            int row1 = row0 + 8;
            if (row1 < mEnd) {
                float u2 = au[mt][nt][2], u3 = au[mt][nt][3];
                float h2 = u2 / (1.f + __expf(-u2)) * av[mt][nt][2];
                float h3 = u3 / (1.f + __expf(-u3)) * av[mt][nt][3];
                *(__half2*)&g_h[(size_t)row1 * HID + col] = __floats2half2_rn(h2, h3);
            }
        }
    }
}

// ---------------- down: y[token] = gate * (H @ Wd[e]) ------------------------
__global__ __launch_bounds__(256) void dn_mma(const float* __restrict__ Wd,
                                              float* __restrict__ out) {
    int e    = blockIdx.z;
    int mEnd = g_off[e + 1];
    int m0   = g_off[e] + blockIdx.x * 128;
    if (m0 >= mEnd) return;
    int n0 = blockIdx.y * 64;

    __shared__ __align__(16) __half As[2][128 * AST];
    __shared__ __align__(16) __half Bs[2][32 * BST];

    int tid = threadIdx.x, lane = tid & 31, wid = tid >> 5;
    int wm = wid & 3, wn = wid >> 2;
    int lg = lane >> 2, lt = lane & 3;

    uint32_t aA[2] = { smem_u32(As[0]), smem_u32(As[1]) };
    uint32_t aB[2] = { smem_u32(Bs[0]), smem_u32(Bs[1]) };

    const float* WdE = Wd + (size_t)e * HID * DMODEL;

    float acc[2][4][4];
#pragma unroll
    for (int mt = 0; mt < 2; mt++)
#pragma unroll
        for (int nt = 0; nt < 4; nt++)
#pragma unroll
            for (int r = 0; r < 4; r++) acc[mt][nt][r] = 0.f;

    int brow = tid >> 3, bcol = (tid & 7) * 8;
    float pb[8];

    auto issueA = [&](int c, int st) {
#pragma unroll
        for (int q = 0; q < 2; q++) {
            int sidx = tid + q * 256;
            int row = sidx >> 2, sg = sidx & 3;
            int gm = m0 + row;
            bool v = gm < mEnd;
            uint32_t dst = aA[st] + (uint32_t)(row * AST + sg * 8) * 2;
            const __half* src = &g_h[(size_t)(v ? gm : m0) * HID + c * 32 + sg * 8];
            cpa16(dst, src, v);
        }
    };
    auto ldgB = [&](int c) {
        const float* rb = &WdE[(size_t)(c * 32 + brow) * DMODEL + n0 + bcol];
        *(float4*)&pb[0] = *(const float4*)rb;  *(float4*)&pb[4] = *(const float4*)(rb + 4);
    };
    auto stsB = [&](int st) {
        *(uint4*)&Bs[st][brow * BST + bcol] =
            make_uint4(pk(pb[0], pb[1]), pk(pb[2], pb[3]), pk(pb[4], pb[5]), pk(pb[6], pb[7]));
    };
    auto ldFragA = [&](int st, int s, uint32_t a[2][4]) {
#pragma unroll
        for (int mt = 0; mt < 2; mt++) {
            uint32_t ad = aA[st] + (uint32_t)(((wm * 32 + mt * 16 + (lane & 15)) * AST)
                                              + s * 16 + (lane >> 4) * 8) * 2;
            LDSM_X4(a[mt][0], a[mt][1], a[mt][2], a[mt][3], ad);
        }
    };
    auto ldFragB = [&](int st, int s, uint32_t b[2][4]) {
#pragma unroll
        for (int np = 0; np < 2; np++) {
            uint32_t bd = aB[st] + (uint32_t)(((s * 16 + (lane & 15)) * BST)
                                              + wn * 32 + np * 16 + (lane >> 4) * 8) * 2;
            LDSM_X4T(b[np][0], b[np][1], b[np][2], b[np][3], bd);
        }
    };
    auto compute = [&](int st) {
        uint32_t a[2][2][4], b[2][2][4];
        ldFragA(st, 0, a[0]);
        ldFragB(st, 0, b[0]);
#pragma unroll
        for (int s = 0; s < 2; s++) {
            int cur = s & 1, nxt = cur ^ 1;
            if (s < 1) { ldFragA(st, s + 1, a[nxt]); ldFragB(st, s + 1, b[nxt]); }
#pragma unroll
            for (int np = 0; np < 2; np++)
#pragma unroll
                for (int mt = 0; mt < 2; mt++) {
                    MMA16816(acc[mt][np * 2 + 0], a[cur][mt], b[cur][np][0], b[cur][np][1]);
                    MMA16816(acc[mt][np * 2 + 1], a[cur][mt], b[cur][np][2], b[cur][np][3]);
                }
        }
    };

    issueA(0, 0); ldgB(0); stsB(0);
    CP_COMMIT(); CP_WAIT0(); __syncthreads();

    for (int c = 0; c < NC_DN; c++) {
        int buf = c & 1;
        bool pf = (c + 1) < NC_DN;
        if (pf) { issueA(c + 1, buf ^ 1); ldgB(c + 1); }
        compute(buf);
        if (pf) stsB(buf ^ 1);
        CP_COMMIT(); CP_WAIT0(); __syncthreads();
    }

#pragma unroll
    for (int mt = 0; mt < 2; mt++) {
#pragma unroll
        for (int nt = 0; nt < 4; nt++) {
            int row0 = m0 + wm * 32 + mt * 16 + lg;
            int col  = n0 + wn * 32 + nt * 8 + lt * 2;
            if (row0 < mEnd) {
                int token = g_tok[row0];
                float gate = g_gate[token];
                *(float2*)&out[(size_t)token * DMODEL + col] =
                    make_float2(acc[mt][nt][0] * gate, acc[mt][nt][1] * gate);
            }
            int row1 = row0 + 8;
            if (row1 < mEnd) {
                int token = g_tok[row1];
                float gate = g_gate[token];
                *(float2*)&out[(size_t)token * DMODEL + col] =
                    make_float2(acc[mt][nt][2] * gate, acc[mt][nt][3] * gate);
            }
        }
    }
}

// ---------------- aux --------------------------------------------------------
__global__ void aux_kernel(float* __restrict__ out) {
    float s = 0.f;
    for (int e = 0; e < NE; e++) {
        float me = (float)g_counts[e] / (float)T_TOK;
        float ce = g_ce[e] / (float)T_TOK;
        s += me * ce;
    }
    out[(size_t)T_TOK * DMODEL] = ALPHA * NE * s;
}

// ---------------- launch -----------------------------------------------------
extern "C" void kernel_launch(void* const* d_in, const int* in_sizes, int n_in,
                              void* d_out, int out_size) {
    const float* x   = (const float*)d_in[0];
    const float* wgw = (const float*)d_in[1];
    const float* wgb = (const float*)d_in[2];
    const float* Wu  = (const float*)d_in[3];
    const float* Wv  = (const float*)d_in[4];
    const float* Wd  = (const float*)d_in[5];
    float* out = (float*)d_out;

    init_kernel<<<1, 32>>>();
    gate_kernel<<<T_TOK / 8, 256>>>(x, wgw, wgb);
    scan_kernel<<<1, 1>>>();
    gather_kernel<<<T_TOK, 192>>>(x);
    up_mma<<<dim3(T_TOK / 128, HID / 64, NE), 256>>>(Wu, Wv);
    dn_mma<<<dim3(T_TOK / 128, DMODEL / 64, NE), 256>>>(Wd, out);
    aux_kernel<<<1, 1>>>(out);
}